// round 8
// baseline (speedup 1.0000x reference)
#include <cuda_runtime.h>

// MaskRCNN RPN, GT-centric split v2:
//  K1: streaming scores/boxes/anchors + labels=0 (no GT loop), ILP-4.
//  K2: per-(b,gt,level,atype) scatter, candidate rect flattened across lanes,
//      float guard-band fast path, exact fp64 only in the ambiguous band.

#define B_   2
#define A_   20
#define NTOT 261888

#define OUT_SC 0
#define OUT_BX (B_ * NTOT * 2)
#define OUT_AN (OUT_BX + B_ * NTOT * 4)
#define OUT_LB (OUT_AN + B_ * NTOT * 4)

struct LvlPtrs {
    const float* cs[5];
    const float* bp[5];
};

__global__ void __launch_bounds__(256)
rpn_stream_kernel(LvlPtrs p, float* __restrict__ out)
{
    int t = blockIdx.x * blockDim.x + threadIdx.x;
    int gid = t * 4;
    if (gid >= B_ * NTOT) return;

    int b = (gid >= NTOT) ? 1 : 0;
    int n = gid - b * NTOT;

    int lvl, offv;
    if      (n < 196608) { lvl = 0; offv = 0;      }
    else if (n < 245760) { lvl = 1; offv = 196608; }
    else if (n < 258048) { lvl = 2; offv = 245760; }
    else if (n < 261120) { lvl = 3; offv = 258048; }
    else                 { lvl = 4; offv = 261120; }

    int log2w  = 8 - lvl;
    int log2hw = 2 * log2w;
    int hw     = 1 << log2hw;

    int local = n - offv;
    int a   = local >> log2hw;
    int rem = local & (hw - 1);
    int y   = rem >> log2w;
    int x0  = rem & ((1 << log2w) - 1);

    float s    = (float)(1 << (lvl + 2));
    float half = 0.5f * (s - 1.0f);
    float base = (float)(1 << (lvl + 6));
    float cy  = s * (float)y + half;
    float cx0 = s * (float)x0 + half;
    float hh = (a == 2) ? 2.0f * base : base;
    float ww = (a == 0) ? 2.0f * base : base;

    const float* csp = p.cs[lvl];
    const float* bpp = p.bp[lvl];
    int cbase = (b * 6  + a * 2) * hw + rem;
    int bbase = (b * 12 + a * 4) * hw + rem;

    float4 c0 = *reinterpret_cast<const float4*>(csp + cbase);
    float4 c1 = *reinterpret_cast<const float4*>(csp + cbase + hw);
    float4 dy = *reinterpret_cast<const float4*>(bpp + bbase);
    float4 dx = *reinterpret_cast<const float4*>(bpp + bbase + hw);
    float4 dh = *reinterpret_cast<const float4*>(bpp + bbase + 2 * hw);
    float4 dw = *reinterpret_cast<const float4*>(bpp + bbase + 3 * hw);

    long long row = (long long)b * NTOT + n;

    float4* sc = reinterpret_cast<float4*>(out + OUT_SC + row * 2);
    sc[0] = make_float4(c0.x, c1.x, c0.y, c1.y);
    sc[1] = make_float4(c0.z, c1.z, c0.w, c1.w);

    float dyv[4] = {dy.x, dy.y, dy.z, dy.w};
    float dxv[4] = {dx.x, dx.y, dx.z, dx.w};
    float dhv[4] = {dh.x, dh.y, dh.z, dh.w};
    float dwv[4] = {dw.x, dw.y, dw.z, dw.w};

    float4* bx = reinterpret_cast<float4*>(out + OUT_BX + row * 4);
    float4* an = reinterpret_cast<float4*>(out + OUT_AN + row * 4);

#pragma unroll
    for (int j = 0; j < 4; ++j) {
        float cxj = cx0 + (float)j * s;
        float cyc = cy  + dyv[j] * hh;
        float cxc = cxj + dxv[j] * ww;
        float h2  = hh * __expf(dhv[j]);
        float w2  = ww * __expf(dwv[j]);
        bx[j] = make_float4(cyc - 0.5f * h2, cxc - 0.5f * w2,
                            cyc + 0.5f * h2, cxc + 0.5f * w2);
        an[j] = make_float4(cy, cxj, hh, ww);
    }

    *reinterpret_cast<float4*>(out + OUT_LB + row) =
        make_float4(0.0f, 0.0f, 0.0f, 0.0f);
}

__constant__ int c_offv[5] = {0, 196608, 245760, 258048, 261120};

__global__ void __launch_bounds__(32)
rpn_label_scatter(const float* __restrict__ gt,
                  const int* __restrict__ gtc,
                  float* __restrict__ out)
{
    int unit = blockIdx.x;                    // 600 units, one warp each
    int lane = threadIdx.x;

    int b   = unit / (A_ * 15);
    int r   = unit - b * (A_ * 15);
    int g   = r / 15;
    int r2  = r - g * 15;
    int lvl = r2 / 3;
    int a   = r2 - lvl * 3;

    int cnt = gtc[b];
    cnt = (cnt < 0) ? 0 : (cnt > A_ ? A_ : cnt);
    if (g >= cnt) return;

    const float* gb = gt + (b * A_ + g) * 4;
    float gy1 = gb[0], gx1 = gb[1], gy2 = gb[2], gx2 = gb[3];
    float gh = __fsub_rn(gy2, gy1);
    float gw = __fsub_rn(gx2, gx1);
    float ga = __fmul_rn(gh, gw);

    int log2w = 8 - lvl;
    int w  = 1 << log2w;
    int hw = w * w;
    float s    = (float)(1 << (lvl + 2));
    float half = 0.5f * (s - 1.0f);
    float base = (float)(1 << (lvl + 6));
    float hh = (a == 2) ? 2.0f * base : base;
    float ww = (a == 0) ? 2.0f * base : base;
    float area = __fmul_rn(hh, ww);
    float thr  = __fadd_rn(area, ga);

    // minimum possible intersection for any positive (conservative)
    float req = thr * (1.0f / 3.0f) * 0.9999f;
    if (fminf(area, ga) < req) return;        // size-incompatible: no positives

    float hh2 = 0.5f * hh, ww2 = 0.5f * ww;
    float oy_max = fminf(hh, gh);
    float ox_max = fminf(ww, gw);

    float oy_req = (req / ox_max) * 0.9999f;  // need oy >= this
    float ox_req = (req / oy_max) * 0.9999f;  // need ox >= this

    int ylo = (int)floorf((gy1 + oy_req - hh2 - half) / s) - 1;
    int yhi = (int)ceilf ((gy2 - oy_req + hh2 - half) / s) + 1;
    ylo = max(ylo, 0); yhi = min(yhi, w - 1);
    int xlo = (int)floorf((gx1 + ox_req - ww2 - half) / s) - 1;
    int xhi = (int)ceilf ((gx2 - ox_req + ww2 - half) / s) + 1;
    xlo = max(xlo, 0); xhi = min(xhi, w - 1);
    if (ylo > yhi || xlo > xhi) return;

    int nx = xhi - xlo + 1;
    int ncand = (yhi - ylo + 1) * nx;

    // guard-band thresholds around (area+ga)/3
    float kthr = thr * (1.0f / 3.0f);
    float m_hi = kthr * 1.00002f;
    float m_lo = kthr * 0.99998f;

    int lvlbase = OUT_LB + b * NTOT + c_offv[lvl] + a * hw;

    for (int idx = lane; idx < ncand; idx += 32) {
        int yy = idx / nx;
        int xx = idx - yy * nx;
        int y = ylo + yy;
        int x = xlo + xx;

        float cy  = s * (float)y + half;
        float cx  = s * (float)x + half;
        float ay1 = __fsub_rn(cy, hh2);
        float ay2 = __fadd_rn(ay1, hh);
        float ax1 = __fsub_rn(cx, ww2);
        float ax2 = __fadd_rn(ax1, ww);

        float yy1 = fminf(fmaxf(ay1, gy1), gy2);
        float yy2 = fminf(fmaxf(ay2, gy1), gy2);
        float xx1 = fminf(fmaxf(ax1, gx1), gx2);
        float xx2 = fminf(fmaxf(ax2, gx1), gx2);
        float inter = __fmul_rn(__fsub_rn(yy2, yy1), __fsub_rn(xx2, xx1));

        bool pos;
        if (inter >= m_hi)      pos = true;
        else if (inter < m_lo)  pos = false;
        else {
            // ambiguous band: exact reference-equivalent decision
            float uni = __fsub_rn(thr, inter);
            const double Cd = 0.5 - 0x1p-26;
            pos = ((double)inter >= Cd * (double)uni);
        }
        if (pos) out[lvlbase + y * w + x] = 1.0f;
    }
}

extern "C" void kernel_launch(void* const* d_in, const int* in_sizes, int n_in,
                              void* d_out, int out_size)
{
    LvlPtrs p;
    const float* gt = nullptr;
    const int* gtc = nullptr;
    const int cs_sz[5] = {786432, 196608, 49152, 12288, 3072};
    const int bp_sz[5] = {1572864, 393216, 98304, 24576, 6144};

    for (int k = 0; k < n_in; ++k) {
        int sz = in_sizes[k];
        bool matched = false;
        for (int l = 0; l < 5 && !matched; ++l) {
            if (sz == cs_sz[l]) { p.cs[l] = (const float*)d_in[k]; matched = true; }
            else if (sz == bp_sz[l]) { p.bp[l] = (const float*)d_in[k]; matched = true; }
        }
        if (!matched) {
            if (sz == B_ * A_ * 4) gt = (const float*)d_in[k];
            else if (sz == B_)     gtc = (const int*)d_in[k];
        }
    }

    float* out = (float*)d_out;
    int threads = 256;
    int total_t = (B_ * NTOT) / 4;                  // 130944
    int blocks = (total_t + threads - 1) / threads; // 512
    rpn_stream_kernel<<<blocks, threads>>>(p, out);

    rpn_label_scatter<<<B_ * A_ * 15, 32>>>(gt, gtc, out);  // 600 one-warp blocks
}

// round 9
// speedup vs baseline: 1.0949x; 1.0949x over previous
#include <cuda_runtime.h>

// MaskRCNN RPN, GT-centric split v3:
//  K1: streaming scores/boxes/anchors + labels=0, ILP-2 (occupancy-optimized).
//  K2: per-(b,gt,level,atype) scatter, 8 warps/unit (rows/warp, cols/lane),
//      float guard-band fast path, exact fp64 only in the ambiguous band.

#define B_   2
#define A_   20
#define NTOT 261888

#define OUT_SC 0
#define OUT_BX (B_ * NTOT * 2)
#define OUT_AN (OUT_BX + B_ * NTOT * 4)
#define OUT_LB (OUT_AN + B_ * NTOT * 4)

struct LvlPtrs {
    const float* cs[5];
    const float* bp[5];
};

__global__ void __launch_bounds__(256)
rpn_stream_kernel(LvlPtrs p, float* __restrict__ out)
{
    int t = blockIdx.x * blockDim.x + threadIdx.x;
    int gid = t * 2;
    if (gid >= B_ * NTOT) return;

    int b = (gid >= NTOT) ? 1 : 0;
    int n = gid - b * NTOT;

    int lvl, offv;
    if      (n < 196608) { lvl = 0; offv = 0;      }
    else if (n < 245760) { lvl = 1; offv = 196608; }
    else if (n < 258048) { lvl = 2; offv = 245760; }
    else if (n < 261120) { lvl = 3; offv = 258048; }
    else                 { lvl = 4; offv = 261120; }

    int log2w  = 8 - lvl;
    int log2hw = 2 * log2w;
    int hw     = 1 << log2hw;

    int local = n - offv;
    int a   = local >> log2hw;
    int rem = local & (hw - 1);
    int y   = rem >> log2w;
    int x0  = rem & ((1 << log2w) - 1);

    float s    = (float)(1 << (lvl + 2));
    float half = 0.5f * (s - 1.0f);
    float base = (float)(1 << (lvl + 6));
    float cy  = s * (float)y + half;
    float cx0 = s * (float)x0 + half;
    float hh = (a == 2) ? 2.0f * base : base;
    float ww = (a == 0) ? 2.0f * base : base;

    const float* csp = p.cs[lvl];
    const float* bpp = p.bp[lvl];
    int cbase = (b * 6  + a * 2) * hw + rem;
    int bbase = (b * 12 + a * 4) * hw + rem;

    float2 c0 = *reinterpret_cast<const float2*>(csp + cbase);
    float2 c1 = *reinterpret_cast<const float2*>(csp + cbase + hw);
    float2 dy = *reinterpret_cast<const float2*>(bpp + bbase);
    float2 dx = *reinterpret_cast<const float2*>(bpp + bbase + hw);
    float2 dh = *reinterpret_cast<const float2*>(bpp + bbase + 2 * hw);
    float2 dw = *reinterpret_cast<const float2*>(bpp + bbase + 3 * hw);

    long long row = (long long)b * NTOT + n;

    *reinterpret_cast<float4*>(out + OUT_SC + row * 2) =
        make_float4(c0.x, c1.x, c0.y, c1.y);

    float dyv[2] = {dy.x, dy.y};
    float dxv[2] = {dx.x, dx.y};
    float dhv[2] = {dh.x, dh.y};
    float dwv[2] = {dw.x, dw.y};

    float4* bx = reinterpret_cast<float4*>(out + OUT_BX + row * 4);
    float4* an = reinterpret_cast<float4*>(out + OUT_AN + row * 4);

#pragma unroll
    for (int j = 0; j < 2; ++j) {
        float cxj = cx0 + (float)j * s;
        float cyc = cy  + dyv[j] * hh;
        float cxc = cxj + dxv[j] * ww;
        float h2  = hh * __expf(dhv[j]);
        float w2  = ww * __expf(dwv[j]);
        bx[j] = make_float4(cyc - 0.5f * h2, cxc - 0.5f * w2,
                            cyc + 0.5f * h2, cxc + 0.5f * w2);
        an[j] = make_float4(cy, cxj, hh, ww);
    }

    *reinterpret_cast<float2*>(out + OUT_LB + row) = make_float2(0.0f, 0.0f);
}

__constant__ int c_offv[5] = {0, 196608, 245760, 258048, 261120};

__global__ void __launch_bounds__(256)
rpn_label_scatter(const float* __restrict__ gt,
                  const int* __restrict__ gtc,
                  float* __restrict__ out)
{
    int unit = blockIdx.x;                    // 600 units, 8 warps each
    int wid  = threadIdx.x >> 5;
    int lane = threadIdx.x & 31;

    int b   = unit / (A_ * 15);
    int r   = unit - b * (A_ * 15);
    int g   = r / 15;
    int r2  = r - g * 15;
    int lvl = r2 / 3;
    int a   = r2 - lvl * 3;

    int cnt = gtc[b];
    cnt = (cnt < 0) ? 0 : (cnt > A_ ? A_ : cnt);
    if (g >= cnt) return;

    const float* gb = gt + (b * A_ + g) * 4;
    float gy1 = gb[0], gx1 = gb[1], gy2 = gb[2], gx2 = gb[3];
    float gh = __fsub_rn(gy2, gy1);
    float gw = __fsub_rn(gx2, gx1);
    float ga = __fmul_rn(gh, gw);

    int log2w = 8 - lvl;
    int w  = 1 << log2w;
    int hw = w * w;
    float s    = (float)(1 << (lvl + 2));
    float half = 0.5f * (s - 1.0f);
    float base = (float)(1 << (lvl + 6));
    float hh = (a == 2) ? 2.0f * base : base;
    float ww = (a == 0) ? 2.0f * base : base;
    float area = __fmul_rn(hh, ww);
    float thr  = __fadd_rn(area, ga);

    // minimum possible intersection for any positive (conservative)
    float req = thr * (1.0f / 3.0f) * 0.9999f;
    if (fminf(area, ga) < req) return;        // size-incompatible: no positives

    float hh2 = 0.5f * hh, ww2 = 0.5f * ww;
    float oy_max = fminf(hh, gh);
    float ox_max = fminf(ww, gw);

    float oy_req = (req / ox_max) * 0.9999f;  // need oy >= this
    float ox_req = (req / oy_max) * 0.9999f;  // need ox >= this

    int ylo = (int)floorf((gy1 + oy_req - hh2 - half) / s) - 1;
    int yhi = (int)ceilf ((gy2 - oy_req + hh2 - half) / s) + 1;
    ylo = max(ylo, 0); yhi = min(yhi, w - 1);
    int xlo = (int)floorf((gx1 + ox_req - ww2 - half) / s) - 1;
    int xhi = (int)ceilf ((gx2 - ox_req + ww2 - half) / s) + 1;
    xlo = max(xlo, 0); xhi = min(xhi, w - 1);
    if (ylo > yhi || xlo > xhi) return;

    // guard-band thresholds around (area+ga)/3
    float kthr = thr * (1.0f / 3.0f);
    float m_hi = kthr * 1.00002f;
    float m_lo = kthr * 0.99998f;

    int lvlbase = OUT_LB + b * NTOT + c_offv[lvl] + a * hw;

    for (int y = ylo + wid; y <= yhi; y += 8) {
        float cy  = s * (float)y + half;
        float ay1 = __fsub_rn(cy, hh2);
        float ay2 = __fadd_rn(ay1, hh);
        float yy1 = fminf(fmaxf(ay1, gy1), gy2);
        float yy2 = fminf(fmaxf(ay2, gy1), gy2);
        float oy  = __fsub_rn(yy2, yy1);
        if (__fmul_rn(oy, ox_max) < req) continue;

        int rowbase = lvlbase + y * w;
        for (int x = xlo + lane; x <= xhi; x += 32) {
            float cx  = s * (float)x + half;
            float ax1 = __fsub_rn(cx, ww2);
            float ax2 = __fadd_rn(ax1, ww);
            float xx1 = fminf(fmaxf(ax1, gx1), gx2);
            float xx2 = fminf(fmaxf(ax2, gx1), gx2);
            float inter = __fmul_rn(oy, __fsub_rn(xx2, xx1));

            bool pos;
            if (inter >= m_hi)      pos = true;
            else if (inter < m_lo)  pos = false;
            else {
                // ambiguous band: exact reference-equivalent decision
                float uni = __fsub_rn(thr, inter);
                const double Cd = 0.5 - 0x1p-26;
                pos = ((double)inter >= Cd * (double)uni);
            }
            if (pos) out[rowbase + x] = 1.0f;
        }
    }
}

extern "C" void kernel_launch(void* const* d_in, const int* in_sizes, int n_in,
                              void* d_out, int out_size)
{
    LvlPtrs p;
    const float* gt = nullptr;
    const int* gtc = nullptr;
    const int cs_sz[5] = {786432, 196608, 49152, 12288, 3072};
    const int bp_sz[5] = {1572864, 393216, 98304, 24576, 6144};

    for (int k = 0; k < n_in; ++k) {
        int sz = in_sizes[k];
        bool matched = false;
        for (int l = 0; l < 5 && !matched; ++l) {
            if (sz == cs_sz[l]) { p.cs[l] = (const float*)d_in[k]; matched = true; }
            else if (sz == bp_sz[l]) { p.bp[l] = (const float*)d_in[k]; matched = true; }
        }
        if (!matched) {
            if (sz == B_ * A_ * 4) gt = (const float*)d_in[k];
            else if (sz == B_)     gtc = (const int*)d_in[k];
        }
    }

    float* out = (float*)d_out;
    int threads = 256;
    int total_t = (B_ * NTOT) / 2;                  // 261888
    int blocks = (total_t + threads - 1) / threads; // 1023
    rpn_stream_kernel<<<blocks, threads>>>(p, out);

    rpn_label_scatter<<<B_ * A_ * 15, 256>>>(gt, gtc, out);  // 600 blocks x 8 warps
}